// round 10
// baseline (speedup 1.0000x reference)
#include <cuda_runtime.h>
#include <cuda_bf16.h>
#include <cstdint>

// VACF via band-Gram, parallelogram tiling on mma.sync bf16.
// f32 data register-prefetched from global (no smem staging, no cp.async);
// f32->bf16 hi/lo split convert staggered by warp parity; 1 barrier/chunk.
// 512 thr/CTA, 1 CTA/SM, 148 CTAs, chunk-balanced; last-CTA finalize.
// S[t] = sum_i x_i . x_{i+t}; x = hi + lo (bf16); 3 passes hh+hl+lh.

#define T_DIM 10000
#define D_DIM 3000
#define D4    750                // D_DIM/4
#define NTILE 79
#define NCHT  94                 // K chunks of 32 elems
#define UNITS (NTILE * NCHT)     // 7426
#define NCTA  148
#define NTHREADS 512
#define W_MAX 100
#define RB    240                // rows per tile (128 + halo)
#define STRB    80               // bf16 smem row stride (bytes)
#define HTILE_B (RB * STRB)      // 19200
#define STAGE_B (2 * HTILE_B)    // hi + lo = 38400
#define SMEM_B  (2 * STAGE_B)    // 76800

__device__ double g_band[128];
__device__ unsigned g_done;

__device__ __forceinline__ void ldsm4(unsigned a, unsigned& r0, unsigned& r1,
                                      unsigned& r2, unsigned& r3) {
    asm volatile("ldmatrix.sync.aligned.m8n8.x4.shared.b16 {%0,%1,%2,%3}, [%4];"
                 : "=r"(r0), "=r"(r1), "=r"(r2), "=r"(r3) : "r"(a));
}

__device__ __forceinline__ void mma16816(float* c, const unsigned* a, const unsigned* b) {
    asm("mma.sync.aligned.m16n8k16.row.col.f32.bf16.bf16.f32 "
        "{%0,%1,%2,%3}, {%4,%5,%6,%7}, {%8,%9}, {%0,%1,%2,%3};"
        : "+f"(c[0]), "+f"(c[1]), "+f"(c[2]), "+f"(c[3])
        : "r"(a[0]), "r"(a[1]), "r"(a[2]), "r"(a[3]), "r"(b[0]), "r"(b[1]));
}

__global__ __launch_bounds__(NTHREADS, 1) void vacf_gram(const float* __restrict__ vel,
                                                         float* __restrict__ out, int W) {
    extern __shared__ __align__(128) char sm[];
    __shared__ float s_band[W_MAX];
    __shared__ int s_last;

    const int tid  = threadIdx.x;
    const int warp = tid >> 5;
    const int lane = tid & 31;
    const int gB   = blockIdx.x;

    const unsigned smu = (unsigned)__cvta_generic_to_shared(sm);

    if (tid < W_MAX) s_band[tid] = 0.f;

    // consumer tiling (same fragment layout as R8)
    const int strip = warp >> 1;
    const int njpb  = (warp & 1) * 4;
    const int rl = lane & 7, gg = lane >> 3;
    const int arow  = 16 * strip + rl + ((gg & 1) << 3);
    const int acol0 = (gg >> 1) << 3;
    const int brow0 = 16 * strip + rl + ((gg >> 1) << 3);
    const int bcol0 = (gg & 1) << 3;

    // per-thread load/convert slots: sid = tid + 512k, k = 0..3 (sid < 1920)
    int srow[4], sseg[4], svalid[4];
    unsigned soff[4];
    #pragma unroll
    for (int k = 0; k < 4; k++) {
        int sid = tid + (k << 9);
        svalid[k] = (sid < RB * 8);
        srow[k] = sid >> 3;
        sseg[k] = sid & 7;
        soff[k] = (unsigned)(srow[k] * STRB + sseg[k] * 8);
    }

    int u  = (int)(((long)gB * UNITS) / NCTA);
    const int u1 = (int)(((long)(gB + 1) * UNITS) / NCTA);

    float c[8][4];
    float4 pf[4];

    while (u < u1) {
        const int tile = u / NCHT;
        const int cbeg = u % NCHT;
        const int cend = (cbeg + (u1 - u) < NCHT) ? cbeg + (u1 - u) : NCHT;
        const int R0   = tile * 128;
        u += cend - cbeg;

        // per-segment row pointers (clamped) + row validity
        const float* rptr[4];
        int rok[4];
        #pragma unroll
        for (int k = 0; k < 4; k++) {
            int gr = R0 + srow[k];
            rok[k] = svalid[k] && (gr < T_DIM);
            int grc = (gr < T_DIM) ? gr : (T_DIM - 1);
            rptr[k] = vel + (size_t)grc * D_DIM + sseg[k] * 4;
        }

        #pragma unroll
        for (int i = 0; i < 8; i++)
            #pragma unroll
            for (int q = 0; q < 4; q++) c[i][q] = 0.f;

        // register prefetch of chunk ci (f32)
        auto prefetch = [&](int ci) {
            #pragma unroll
            for (int k = 0; k < 4; k++) {
                int c4 = ci * 8 + sseg[k];
                bool ok = rok[k] && (c4 < D4);
                const float4* p = reinterpret_cast<const float4*>(
                    rptr[k] + (ok ? ci * 32 : 0));
                float4 v = *p;
                if (!ok) v = make_float4(0.f, 0.f, 0.f, 0.f);
                pf[k] = v;
            }
        };

        // convert prefetched regs -> bf16 hi/lo stage si
        auto convert = [&](int si) {
            const unsigned hib = (unsigned)(si * STAGE_B);
            #pragma unroll
            for (int k = 0; k < 4; k++) {
                if (svalid[k]) {
                    const float4 v = pf[k];
                    __nv_bfloat162 h01 = __float22bfloat162_rn(make_float2(v.x, v.y));
                    __nv_bfloat162 h23 = __float22bfloat162_rn(make_float2(v.z, v.w));
                    float l0 = v.x - __bfloat162float(h01.x);
                    float l1 = v.y - __bfloat162float(h01.y);
                    float l2 = v.z - __bfloat162float(h23.x);
                    float l3 = v.w - __bfloat162float(h23.y);
                    __nv_bfloat162 q01 = __float22bfloat162_rn(make_float2(l0, l1));
                    __nv_bfloat162 q23 = __float22bfloat162_rn(make_float2(l2, l3));
                    uint2 hh, ll;
                    hh.x = *reinterpret_cast<unsigned*>(&h01);
                    hh.y = *reinterpret_cast<unsigned*>(&h23);
                    ll.x = *reinterpret_cast<unsigned*>(&q01);
                    ll.y = *reinterpret_cast<unsigned*>(&q23);
                    *reinterpret_cast<uint2*>(sm + hib + soff[k]) = hh;
                    *reinterpret_cast<uint2*>(sm + hib + HTILE_B + soff[k]) = ll;
                }
            }
        };

        auto bstep = [&](unsigned hib, unsigned lob, int kk, int jl,
                         unsigned* ahi, unsigned* alo) {
            const int njp = njpb + jl;
            unsigned boff = (unsigned)((brow0 + njp * 16) * STRB + (kk + bcol0) * 2);
            unsigned bhi[4], blo[4];
            ldsm4(hib + boff, bhi[0], bhi[1], bhi[2], bhi[3]);
            ldsm4(lob + boff, blo[0], blo[1], blo[2], blo[3]);
            const int lj = jl * 2;
            const bool has2 = (njp * 2 + 1) < 15;
            mma16816(c[lj], ahi, &bhi[0]);
            if (has2) mma16816(c[lj + 1], ahi, &bhi[2]);
            mma16816(c[lj], ahi, &blo[0]);
            if (has2) mma16816(c[lj + 1], ahi, &blo[2]);
            mma16816(c[lj], alo, &bhi[0]);
            if (has2) mma16816(c[lj + 1], alo, &bhi[2]);
        };

        // ---- prologue: stage chunk cbeg ----
        prefetch(cbeg);
        convert(0);
        __syncthreads();

        for (int ci = cbeg; ci < cend; ci++) {
            const int si = (ci - cbeg) & 1;
            const unsigned hib = smu + (unsigned)(si * STAGE_B);
            const unsigned lob = hib + HTILE_B;
            const bool havenext = (ci + 1 < cend);

            // issue prefetch of next chunk early (latency hidden under mma)
            if (havenext) prefetch(ci + 1);

            // ks = 0
            {
                unsigned aoff = (unsigned)(arow * STRB + acol0 * 2);
                unsigned ahi[4], alo[4];
                ldsm4(hib + aoff, ahi[0], ahi[1], ahi[2], ahi[3]);
                ldsm4(lob + aoff, alo[0], alo[1], alo[2], alo[3]);
                #pragma unroll
                for (int jl = 0; jl < 4; jl++)
                    bstep(hib, lob, 0, jl, ahi, alo);
            }

            // even warps convert here (staggered)
            if (havenext && !(warp & 1)) convert(si ^ 1);

            // ks = 1
            {
                unsigned aoff = (unsigned)(arow * STRB + (16 + acol0) * 2);
                unsigned ahi[4], alo[4];
                ldsm4(hib + aoff, ahi[0], ahi[1], ahi[2], ahi[3]);
                ldsm4(lob + aoff, alo[0], alo[1], alo[2], alo[3]);
                #pragma unroll
                for (int jl = 0; jl < 4; jl++)
                    bstep(hib, lob, 16, jl, ahi, alo);
            }

            // odd warps convert here (staggered)
            if (havenext && (warp & 1)) convert(si ^ 1);

            // single barrier: publishes stage si^1, retires ldsm of stage si
            __syncthreads();
        }

        // ---- segment epilogue: band extraction ----
        #pragma unroll
        for (int jl = 0; jl < 4; jl++)
            #pragma unroll
            for (int j = 0; j < 2; j++) {
                const int nj = (njpb + jl) * 2 + j;
                if (nj < 15)
                    #pragma unroll
                    for (int q = 0; q < 4; q++) {
                        int t = nj * 8 + ((lane & 3) << 1) + (q & 1)
                              - (lane >> 2) - ((q >> 1) << 3);
                        if (t >= 0 && t < W_MAX)
                            atomicAdd(&s_band[t], c[jl * 2 + j][q]);
                    }
            }
        __syncthreads();
        if (tid < W_MAX) {
            atomicAdd(&g_band[tid], (double)s_band[tid]);
            s_band[tid] = 0.f;
        }
        __syncthreads();
    }

    // ---- completion protocol: last CTA finalizes ----
    if (tid == 0) {
        __threadfence();
        unsigned p = atomicAdd(&g_done, 1u);
        s_last = (p == NCTA - 1);
    }
    __syncthreads();
    if (s_last) {
        __threadfence();
        if (tid < W_MAX && tid < W)
            out[tid] = (float)(g_band[tid] / ((double)(T_DIM - tid) * (double)D_DIM));
        if (tid < 128) g_band[tid] = 0.0;
        if (tid == 0) g_done = 0;
    }
}

extern "C" void kernel_launch(void* const* d_in, const int* in_sizes, int n_in,
                              void* d_out, int out_size) {
    const float* vel = (const float*)d_in[0];
    cudaFuncSetAttribute(vacf_gram, cudaFuncAttributeMaxDynamicSharedMemorySize, SMEM_B);
    vacf_gram<<<NCTA, NTHREADS, SMEM_B>>>(vel, (float*)d_out, out_size);
}